// round 1
// baseline (speedup 1.0000x reference)
#include <cuda_runtime.h>
#include <math.h>

#define NB   8
#define NC   1536
#define NHD  8
#define HWSZ 1024
#define NG   24
#define CPG  64

// Per-(batch, channel) fused GroupNorm affine: y = x*scale + shift
__device__ float g_scale[NB * NC];
__device__ float g_shift[NB * NC];

// ---------------------------------------------------------------------------
// Kernel A: per-(b, group) stats -> per-(b, channel) affine coefficients
// ---------------------------------------------------------------------------
__global__ void gn_stats_kernel(const float* __restrict__ x,
                                const float* __restrict__ w,
                                const float* __restrict__ bs) {
    const int b = blockIdx.x / NG;
    const int g = blockIdx.x % NG;
    const float4* p = (const float4*)(x + ((size_t)b * NC + (size_t)g * CPG) * HWSZ);

    float s = 0.f, ss = 0.f;
    for (int i = threadIdx.x; i < (CPG * HWSZ) / 4; i += 256) {
        float4 v = p[i];
        s  += v.x + v.y + v.z + v.w;
        ss += v.x * v.x + v.y * v.y + v.z * v.z + v.w * v.w;
    }
    __shared__ float rs[256], rq[256];
    rs[threadIdx.x] = s;
    rq[threadIdx.x] = ss;
    __syncthreads();
    for (int off = 128; off > 0; off >>= 1) {
        if (threadIdx.x < off) {
            rs[threadIdx.x] += rs[threadIdx.x + off];
            rq[threadIdx.x] += rq[threadIdx.x + off];
        }
        __syncthreads();
    }
    if (threadIdx.x < CPG) {
        const float inv_n = 1.f / (float)(CPG * HWSZ);
        float mean = rs[0] * inv_n;
        float var  = rq[0] * inv_n - mean * mean;
        float rstd = rsqrtf(var + 1e-5f);
        int c = g * CPG + threadIdx.x;
        float sc = rstd * w[c];
        g_scale[b * NC + c] = sc;
        g_shift[b * NC + c] = bs[c] - mean * sc;
    }
}

// ---------------------------------------------------------------------------
// Kernel B: flash attention. grid = (16 q-tiles, 64 bh), 256 threads.
// SMEM: Qs[64][64], Ks[64][64], Vt[64][64] (k-pos major), Pt[64][68] (P^T).
// Thread (ty=tid>>4, tx=tid&15) owns 4x4 micro-tiles.
// ---------------------------------------------------------------------------
__global__ __launch_bounds__(256) void attn_kernel(const float* __restrict__ x,
                                                   float* __restrict__ out) {
    extern __shared__ float sm[];
    float* Qs = sm;              // 4096
    float* Ks = sm + 4096;       // 4096
    float* Vt = sm + 8192;       // 4096, Vt[j][vd]
    float* Pt = sm + 12288;      // 64*68 = 4352, Pt[j][i] (also output staging)
    __shared__ float sSc[192], sSh[192];

    const int tid = threadIdx.x;
    const int bh  = blockIdx.y;
    const int b   = bh >> 3, h = bh & 7;
    const int q0  = blockIdx.x * 64;
    const float* base = x + ((size_t)b * NC + (size_t)h * 192) * HWSZ;

    if (tid < 192) {
        int cg = b * NC + h * 192 + tid;
        sSc[tid] = g_scale[cg];
        sSh[tid] = g_shift[cg];
    }
    __syncthreads();

    // Load Q tile (fold GN affine and 1/sqrt(64) = 0.125)
    #pragma unroll
    for (int k = 0; k < 4; k++) {
        int idx = tid + k * 256;          // float4 index 0..1023
        int c = idx >> 4, f = (idx & 15) * 4;
        float4 v = *(const float4*)(base + (size_t)(64 + c) * HWSZ + q0 + f);
        float sc = sSc[64 + c] * 0.125f, sh = sSh[64 + c] * 0.125f;
        v.x = v.x * sc + sh; v.y = v.y * sc + sh;
        v.z = v.z * sc + sh; v.w = v.w * sc + sh;
        *(float4*)&Qs[c * 64 + f] = v;
    }

    const int ty = tid >> 4, tx = tid & 15;
    float m[4], l[4], o[4][4];
    #pragma unroll
    for (int u = 0; u < 4; u++) {
        m[u] = -INFINITY; l[u] = 0.f;
        #pragma unroll
        for (int v = 0; v < 4; v++) o[u][v] = 0.f;
    }

    for (int kt = 0; kt < 16; kt++) {
        __syncthreads();   // prior iteration done reading Ks/Vt/Pt

        // K tile (coalesced)
        #pragma unroll
        for (int k = 0; k < 4; k++) {
            int idx = tid + k * 256;
            int c = idx >> 4, f = (idx & 15) * 4;
            float4 v = *(const float4*)(base + (size_t)c * HWSZ + kt * 64 + f);
            float sc = sSc[c], sh = sSh[c];
            v.x = v.x * sc + sh; v.y = v.y * sc + sh;
            v.z = v.z * sc + sh; v.w = v.w * sc + sh;
            *(float4*)&Ks[c * 64 + f] = v;
        }
        // V tile, transposed into Vt[j][vd]
        {
            int vd = tid & 63;
            int jb = (tid >> 6) * 16;
            const float* vp = base + (size_t)(128 + vd) * HWSZ + kt * 64 + jb;
            float sc = sSc[128 + vd], sh = sSh[128 + vd];
            #pragma unroll
            for (int u = 0; u < 16; u += 4) {
                float4 v = *(const float4*)(vp + u);
                Vt[(jb + u + 0) * 64 + vd] = v.x * sc + sh;
                Vt[(jb + u + 1) * 64 + vd] = v.y * sc + sh;
                Vt[(jb + u + 2) * 64 + vd] = v.z * sc + sh;
                Vt[(jb + u + 3) * 64 + vd] = v.w * sc + sh;
            }
        }
        __syncthreads();

        // S = Q^T K  (both operands channel-major in SMEM)
        float s[4][4];
        #pragma unroll
        for (int u = 0; u < 4; u++)
            #pragma unroll
            for (int v = 0; v < 4; v++) s[u][v] = 0.f;

        #pragma unroll 8
        for (int c = 0; c < 64; c++) {
            float4 qv = *(const float4*)&Qs[c * 64 + ty * 4];
            float4 kv = *(const float4*)&Ks[c * 64 + tx * 4];
            float qa[4] = {qv.x, qv.y, qv.z, qv.w};
            float ka[4] = {kv.x, kv.y, kv.z, kv.w};
            #pragma unroll
            for (int u = 0; u < 4; u++)
                #pragma unroll
                for (int v = 0; v < 4; v++) s[u][v] += qa[u] * ka[v];
        }

        // Online softmax: rows i = 4*ty+u shared by the 16 lanes with equal ty
        float mn[4], al[4];
        #pragma unroll
        for (int u = 0; u < 4; u++) {
            float r = fmaxf(fmaxf(s[u][0], s[u][1]), fmaxf(s[u][2], s[u][3]));
            r = fmaxf(r, __shfl_xor_sync(0xffffffffu, r, 8));
            r = fmaxf(r, __shfl_xor_sync(0xffffffffu, r, 4));
            r = fmaxf(r, __shfl_xor_sync(0xffffffffu, r, 2));
            r = fmaxf(r, __shfl_xor_sync(0xffffffffu, r, 1));
            mn[u] = fmaxf(m[u], r);
            al[u] = __expf(m[u] - mn[u]);
            m[u]  = mn[u];
        }
        #pragma unroll
        for (int u = 0; u < 4; u++) {
            #pragma unroll
            for (int v = 0; v < 4; v++) s[u][v] = __expf(s[u][v] - mn[u]);
            float r = s[u][0] + s[u][1] + s[u][2] + s[u][3];
            r += __shfl_xor_sync(0xffffffffu, r, 8);
            r += __shfl_xor_sync(0xffffffffu, r, 4);
            r += __shfl_xor_sync(0xffffffffu, r, 2);
            r += __shfl_xor_sync(0xffffffffu, r, 1);
            l[u] = l[u] * al[u] + r;
        }

        // Store P transposed: Pt[j = 4*tx+v][i = 4*ty..4*ty+3]
        #pragma unroll
        for (int v = 0; v < 4; v++)
            *(float4*)&Pt[(tx * 4 + v) * 68 + ty * 4] =
                make_float4(s[0][v], s[1][v], s[2][v], s[3][v]);

        // Rescale running output
        #pragma unroll
        for (int u = 0; u < 4; u++)
            #pragma unroll
            for (int v = 0; v < 4; v++) o[u][v] *= al[u];

        __syncthreads();

        // O^T[i][vd] += sum_j Pt[j][i] * Vt[j][vd]
        #pragma unroll 8
        for (int j = 0; j < 64; j++) {
            float4 pa = *(const float4*)&Pt[j * 68 + ty * 4];
            float4 vb = *(const float4*)&Vt[j * 64 + tx * 4];
            float pr[4] = {pa.x, pa.y, pa.z, pa.w};
            float vr[4] = {vb.x, vb.y, vb.z, vb.w};
            #pragma unroll
            for (int u = 0; u < 4; u++)
                #pragma unroll
                for (int v = 0; v < 4; v++) o[u][v] += pr[u] * vr[v];
        }
    }

    // Epilogue: normalize, stage via SMEM (Pt reused as Osm[vd][i], stride 68),
    // then coalesced writes.
    float rl[4];
    #pragma unroll
    for (int u = 0; u < 4; u++) rl[u] = 1.f / l[u];
    __syncthreads();
    #pragma unroll
    for (int v = 0; v < 4; v++)
        *(float4*)&Pt[(tx * 4 + v) * 68 + ty * 4] =
            make_float4(o[0][v] * rl[0], o[1][v] * rl[1],
                        o[2][v] * rl[2], o[3][v] * rl[3]);
    __syncthreads();

    float* gout = out + ((size_t)(b * NHD + h) * 64) * HWSZ + q0;
    #pragma unroll
    for (int k = 0; k < 4; k++) {
        int idx = tid + k * 256;
        int vd = idx >> 4, f = (idx & 15) * 4;
        *(float4*)(gout + (size_t)vd * HWSZ + f) = *(const float4*)&Pt[vd * 68 + f];
    }
}

// ---------------------------------------------------------------------------
extern "C" void kernel_launch(void* const* d_in, const int* in_sizes, int n_in,
                              void* d_out, int out_size) {
    const float* x    = (const float*)d_in[0];
    const float* w    = (const float*)d_in[1];
    const float* bias = (const float*)d_in[2];
    float* out = (float*)d_out;

    cudaFuncSetAttribute(attn_kernel,
                         cudaFuncAttributeMaxDynamicSharedMemorySize,
                         16640 * (int)sizeof(float));

    gn_stats_kernel<<<NB * NG, 256>>>(x, w, bias);
    attn_kernel<<<dim3(16, 64), 256, 16640 * sizeof(float)>>>(x, out);
}

// round 5
// speedup vs baseline: 6.9658x; 6.9658x over previous
#include <cuda_runtime.h>
#include <cuda_fp16.h>
#include <cstdint>
#include <math.h>

#define NB   8
#define NC   1536
#define HWSZ 1024
#define NG   24
#define CPG  64

__device__ float g_scale[NB * NC];
__device__ float g_shift[NB * NC];

// ---------------------------------------------------------------------------
// Kernel A: per-(b, group) stats -> per-(b, channel) affine coefficients
// ---------------------------------------------------------------------------
__global__ void gn_stats_kernel(const float* __restrict__ x,
                                const float* __restrict__ w,
                                const float* __restrict__ bs) {
    const int b = blockIdx.x / NG;
    const int g = blockIdx.x % NG;
    const float4* p = (const float4*)(x + ((size_t)b * NC + (size_t)g * CPG) * HWSZ);

    float s = 0.f, ss = 0.f;
    for (int i = threadIdx.x; i < (CPG * HWSZ) / 4; i += 256) {
        float4 v = p[i];
        s  += v.x + v.y + v.z + v.w;
        ss += v.x * v.x + v.y * v.y + v.z * v.z + v.w * v.w;
    }
    __shared__ float rs[256], rq[256];
    rs[threadIdx.x] = s;
    rq[threadIdx.x] = ss;
    __syncthreads();
    for (int off = 128; off > 0; off >>= 1) {
        if (threadIdx.x < off) {
            rs[threadIdx.x] += rs[threadIdx.x + off];
            rq[threadIdx.x] += rq[threadIdx.x + off];
        }
        __syncthreads();
    }
    if (threadIdx.x < CPG) {
        const float inv_n = 1.f / (float)(CPG * HWSZ);
        float mean = rs[0] * inv_n;
        float var  = rq[0] * inv_n - mean * mean;
        float rstd = rsqrtf(var + 1e-5f);
        int c = g * CPG + threadIdx.x;
        float sc = rstd * w[c];
        g_scale[b * NC + c] = sc;
        g_shift[b * NC + c] = bs[c] - mean * sc;
    }
}

// ---------------------------------------------------------------------------
// helpers
// ---------------------------------------------------------------------------
__device__ __forceinline__ uint32_t smem_u32(const void* p) {
    uint32_t a;
    asm("{ .reg .u64 t; cvta.to.shared.u64 t, %1; cvt.u32.u64 %0, t; }"
        : "=r"(a) : "l"(p));
    return a;
}
__device__ __forceinline__ float ex2f(float x) {
    float r; asm("ex2.approx.ftz.f32 %0, %1;" : "=f"(r) : "f"(x)); return r;
}
__device__ __forceinline__ void ldsm4(uint32_t* r, uint32_t addr) {
    asm volatile("ldmatrix.sync.aligned.m8n8.x4.shared.b16 {%0,%1,%2,%3}, [%4];"
                 : "=r"(r[0]), "=r"(r[1]), "=r"(r[2]), "=r"(r[3]) : "r"(addr));
}
__device__ __forceinline__ void ldsm4t(uint32_t* r, uint32_t addr) {
    asm volatile("ldmatrix.sync.aligned.m8n8.x4.trans.shared.b16 {%0,%1,%2,%3}, [%4];"
                 : "=r"(r[0]), "=r"(r[1]), "=r"(r[2]), "=r"(r[3]) : "r"(addr));
}
__device__ __forceinline__ void mma16816(float* d, const uint32_t* a,
                                         uint32_t b0, uint32_t b1) {
    asm volatile(
        "mma.sync.aligned.m16n8k16.row.col.f32.f16.f16.f32 "
        "{%0,%1,%2,%3}, {%4,%5,%6,%7}, {%8,%9}, {%0,%1,%2,%3};"
        : "+f"(d[0]), "+f"(d[1]), "+f"(d[2]), "+f"(d[3])
        : "r"(a[0]), "r"(a[1]), "r"(a[2]), "r"(a[3]), "r"(b0), "r"(b1));
}
// pack two floats into half2 {lo=a, hi=b}
__device__ __forceinline__ uint32_t packh2(float a, float b) {
    uint32_t r;
    asm("cvt.rn.f16x2.f32 %0, %1, %2;" : "=r"(r) : "f"(b), "f"(a));
    return r;
}

// SMEM layout (bytes): Qs half[64][136] @0, Ks half[64][72] @17408,
// Vs half[64][72] @26624. Osm float[64][132] overlays @0 in the epilogue.
#define QS_OFF  0
#define KS_OFF  17408
#define VS_OFF  26624
#define SMEM_SZ 35840

// ---------------------------------------------------------------------------
// Kernel B: HMMA flash attention. grid = (8 q-tiles of 128, 64 bh), 256 thr.
// ---------------------------------------------------------------------------
__global__ __launch_bounds__(256, 2)
void attn_mma(const float* __restrict__ x, float* __restrict__ out) {
    extern __shared__ char smc[];
    __half* Qs = (__half*)(smc + QS_OFF);
    __half* Ks = (__half*)(smc + KS_OFF);
    __half* Vs = (__half*)(smc + VS_OFF);
    float* Osm = (float*)smc;
    __shared__ float sSc[192], sSh[192];

    const uint32_t sb = smem_u32(smc);
    const int tid = threadIdx.x;
    const int wid = tid >> 5, lane = tid & 31;
    const int qbase = wid * 16;
    const int bh = blockIdx.y, b = bh >> 3, h = bh & 7;
    const int q0 = blockIdx.x * 128;
    const float* base = x + ((size_t)b * NC + (size_t)h * 192) * HWSZ;

    if (tid < 192) {
        int cg = b * NC + h * 192 + tid;
        sSc[tid] = g_scale[cg];
        sSh[tid] = g_shift[cg];
    }
    __syncthreads();

    // ---- Q tile: x[64+c][q0..q0+127] -> Qs[c][q], fold GN + 0.125*log2(e) ----
    const float QSC = 0.125f * 1.4426950408889634f;
    #pragma unroll
    for (int k = 0; k < 8; k++) {
        int idx = tid + k * 256;            // 2048 float4s
        int c = idx >> 5, fq = (idx & 31) * 4;
        float4 v = *(const float4*)(base + (size_t)(64 + c) * HWSZ + q0 + fq);
        float sc = sSc[64 + c] * QSC, sh = sSh[64 + c] * QSC;
        uint2 pk;
        pk.x = packh2(v.x * sc + sh, v.y * sc + sh);
        pk.y = packh2(v.z * sc + sh, v.w * sc + sh);
        *(uint2*)&Qs[c * 136 + fq] = pk;
    }
    __syncthreads();

    // ---- Preload Q fragments (persist across all k-tiles) ----
    uint32_t qf[4][4];
    {
        int crow0 = ((lane & 16) >> 1) + (lane & 7);
        int qcol  = qbase + (lane & 8);
        #pragma unroll
        for (int kc = 0; kc < 4; kc++)
            ldsm4t(qf[kc], sb + (uint32_t)((kc * 16 + crow0) * 136 + qcol) * 2);
    }

    float o[8][4];
    #pragma unroll
    for (int i = 0; i < 8; i++)
        #pragma unroll
        for (int j = 0; j < 4; j++) o[i][j] = 0.f;
    float l0 = 0.f, l1 = 0.f;

    const uint32_t kfb = sb + KS_OFF +
        (uint32_t)(((lane & 8) + (lane & 7)) * 72 + ((lane & 16) >> 1)) * 2;
    const uint32_t vfb = sb + VS_OFF +
        (uint32_t)((((lane & 16) >> 1) + (lane & 7)) * 72 + (lane & 8)) * 2;

    for (int kt = 0; kt < 16; kt++) {
        const int j0 = kt * 64;
        if (kt > 0) __syncthreads();        // done reading prev K/V

        // ---- K tile: x[c][j0..] -> Ks[c][j];  V tile: x[128+vd][j0..] -> Vs[vd][j]
        #pragma unroll
        for (int k = 0; k < 4; k++) {
            int idx = tid + k * 256;        // 1024 float4s
            int c = idx >> 4, fj = (idx & 15) * 4;
            float4 v = *(const float4*)(base + (size_t)c * HWSZ + j0 + fj);
            float sc = sSc[c], sh = sSh[c];
            uint2 pk;
            pk.x = packh2(v.x * sc + sh, v.y * sc + sh);
            pk.y = packh2(v.z * sc + sh, v.w * sc + sh);
            *(uint2*)&Ks[c * 72 + fj] = pk;
        }
        #pragma unroll
        for (int k = 0; k < 4; k++) {
            int idx = tid + k * 256;
            int vd = idx >> 4, fj = (idx & 15) * 4;
            float4 v = *(const float4*)(base + (size_t)(128 + vd) * HWSZ + j0 + fj);
            float sc = sSc[128 + vd], sh = sSh[128 + vd];
            uint2 pk;
            pk.x = packh2(v.x * sc + sh, v.y * sc + sh);
            pk.y = packh2(v.z * sc + sh, v.w * sc + sh);
            *(uint2*)&Vs[vd * 72 + fj] = pk;
        }
        __syncthreads();

        // ---- S = Q K^T : 8 n-tiles (j), 4 k-chunks (c) ----
        float s[8][4];
        #pragma unroll
        for (int i = 0; i < 8; i++)
            #pragma unroll
            for (int j = 0; j < 4; j++) s[i][j] = 0.f;

        #pragma unroll
        for (int p = 0; p < 4; p++) {
            #pragma unroll
            for (int kc = 0; kc < 4; kc++) {
                uint32_t kb[4];
                ldsm4t(kb, kfb + (uint32_t)(kc * 16 * 72 + p * 16) * 2);
                mma16816(s[2 * p],     qf[kc], kb[0], kb[1]);
                mma16816(s[2 * p + 1], qf[kc], kb[2], kb[3]);
            }
        }

        // ---- softmax numerator: P = exp2(S), running row sums ----
        uint32_t ph[8][2];
        #pragma unroll
        for (int jn = 0; jn < 8; jn++) {
            float e0 = ex2f(s[jn][0]), e1 = ex2f(s[jn][1]);
            float e2 = ex2f(s[jn][2]), e3 = ex2f(s[jn][3]);
            l0 += e0 + e1;
            l1 += e2 + e3;
            ph[jn][0] = packh2(e0, e1);
            ph[jn][1] = packh2(e2, e3);
        }

        // ---- O += P V^T : 8 n-tiles (vd), 4 k-chunks (j) ----
        #pragma unroll
        for (int vp = 0; vp < 4; vp++) {
            #pragma unroll
            for (int jc = 0; jc < 4; jc++) {
                uint32_t vb[4];
                ldsm4(vb, vfb + (uint32_t)(vp * 16 * 72 + jc * 16) * 2);
                uint32_t pa[4] = {ph[2 * jc][0], ph[2 * jc][1],
                                  ph[2 * jc + 1][0], ph[2 * jc + 1][1]};
                mma16816(o[2 * vp],     pa, vb[0], vb[1]);
                mma16816(o[2 * vp + 1], pa, vb[2], vb[3]);
            }
        }
    }

    // ---- Epilogue: normalize, stage via SMEM, coalesced store ----
    l0 += __shfl_xor_sync(0xffffffffu, l0, 1);
    l0 += __shfl_xor_sync(0xffffffffu, l0, 2);
    l1 += __shfl_xor_sync(0xffffffffu, l1, 1);
    l1 += __shfl_xor_sync(0xffffffffu, l1, 2);
    float inv0 = 1.f / l0, inv1 = 1.f / l1;

    __syncthreads();       // all warps done with K/V/Q SMEM
    {
        int qa = qbase + (lane >> 2);
        #pragma unroll
        for (int vn = 0; vn < 8; vn++) {
            int vd = vn * 8 + (lane & 3) * 2;
            Osm[vd * 132 + qa]           = o[vn][0] * inv0;
            Osm[(vd + 1) * 132 + qa]     = o[vn][1] * inv0;
            Osm[vd * 132 + qa + 8]       = o[vn][2] * inv1;
            Osm[(vd + 1) * 132 + qa + 8] = o[vn][3] * inv1;
        }
    }
    __syncthreads();

    float* gout = out + ((size_t)(bh * 64)) * HWSZ + q0;
    #pragma unroll
    for (int k = 0; k < 8; k++) {
        int idx = tid + k * 256;            // 2048 float4s
        int vd = idx >> 5, fq = (idx & 31) * 4;
        *(float4*)(gout + (size_t)vd * HWSZ + fq) = *(const float4*)&Osm[vd * 132 + fq];
    }
}

// ---------------------------------------------------------------------------
extern "C" void kernel_launch(void* const* d_in, const int* in_sizes, int n_in,
                              void* d_out, int out_size) {
    const float* x    = (const float*)d_in[0];
    const float* w    = (const float*)d_in[1];
    const float* bias = (const float*)d_in[2];
    float* out = (float*)d_out;

    gn_stats_kernel<<<NB * NG, 256>>>(x, w, bias);
    attn_mma<<<dim3(8, 64), 256, SMEM_SZ>>>(x, out);
}